// round 3
// baseline (speedup 1.0000x reference)
#include <cuda_runtime.h>
#include <cuda_bf16.h>

#define D_DIM     128
#define N_RBF     50
#define K_PAD     52            // padded K (multiple of 4)
#define E_TILE    32            // edges per tile in edge kernel
#define MAX_NODES 50000
#define CUTOFF_F  5.0f
#define PI_OVER_CUTOFF 0.62831853071795864769f

// scatter-sum accumulator (device global scratch; no cudaMalloc allowed)
__device__ float g_acc[(size_t)MAX_NODES * D_DIM];

// ---------------------------------------------------------------------------
// f32x2 packed helpers (Blackwell FFMA2 — only reachable via PTX fma.rn.f32x2)
// ---------------------------------------------------------------------------
__device__ __forceinline__ unsigned long long ffma2(unsigned long long a,
                                                    unsigned long long b,
                                                    unsigned long long c) {
    unsigned long long d;
    asm("fma.rn.f32x2 %0, %1, %2, %3;" : "=l"(d) : "l"(a), "l"(b), "l"(c));
    return d;
}
__device__ __forceinline__ unsigned long long fadd2(unsigned long long a,
                                                    unsigned long long b) {
    unsigned long long d;
    asm("add.rn.f32x2 %0, %1, %2;" : "=l"(d) : "l"(a), "l"(b));
    return d;
}
__device__ __forceinline__ unsigned long long pack2(float lo, float hi) {
    unsigned long long r;
    asm("mov.b64 %0, {%1, %2};" : "=l"(r) : "f"(lo), "f"(hi));
    return r;
}
__device__ __forceinline__ void unpack2(unsigned long long v, float& lo, float& hi) {
    asm("mov.b64 {%0, %1}, %2;" : "=f"(lo), "=f"(hi) : "l"(v));
}

// ---------------------------------------------------------------------------
// Kernel 1: zero the accumulator
// ---------------------------------------------------------------------------
__global__ void zero_kernel(int n4) {
    int i = blockIdx.x * blockDim.x + threadIdx.x;
    if (i < n4) {
        ((float4*)g_acc)[i] = make_float4(0.f, 0.f, 0.f, 0.f);
    }
}

// ---------------------------------------------------------------------------
// Kernel 2: edge kernel (FFMA2 version).
//   Thread t: group g = t>>6 (handles edges e%2==g), dl = t&63 owns dims
//   (2dl, 2dl+1).  W_e pair packed in 52 x 64-bit registers.
//   rbf tile staged duplicated in smem as float2(r,r) so a single LDS.128
//   feeds two FFMA2 (no pack instructions in hot loop).
//   msg staged in smem, scattered with float4 atomicAdd (RED.E.128).
// ---------------------------------------------------------------------------
__global__ void __launch_bounds__(128) edge_kernel(
    const float* __restrict__ rbf,       // [E, 50]
    const float* __restrict__ dist,      // [E]
    const int*   __restrict__ src,       // [E]
    const int*   __restrict__ dst,       // [E]
    const int*   __restrict__ node_type, // [N]
    const float* __restrict__ emb,       // [100, 128]
    const float* __restrict__ W_e,       // [128, 50]
    const float* __restrict__ b_e,       // [128]
    int n_edges)
{
    __shared__ float2 rr_sh[E_TILE][K_PAD];     // duplicated rbf (r,r)
    __shared__ float  msg_sh[E_TILE][D_DIM];
    __shared__ float  w_sh[E_TILE];             // cutoff weight
    __shared__ int    dst_sh[E_TILE];
    __shared__ int    typ_sh[E_TILE];

    const int tid = threadIdx.x;
    const int g   = tid >> 6;        // edge parity group
    const int dl  = tid & 63;        // dim-pair index
    const int d0  = 2 * dl;

    // packed weight pair per k: (W_e[d0][k], W_e[d0+1][k])
    unsigned long long wreg2[K_PAD];
#pragma unroll
    for (int k = 0; k < N_RBF; k++)
        wreg2[k] = pack2(W_e[d0 * N_RBF + k], W_e[(d0 + 1) * N_RBF + k]);
#pragma unroll
    for (int k = N_RBF; k < K_PAD; k++) wreg2[k] = 0ull;
    const float be0 = b_e[d0];
    const float be1 = b_e[d0 + 1];

    const int num_tiles = (n_edges + E_TILE - 1) / E_TILE;
    for (int tile = blockIdx.x; tile < num_tiles; tile += gridDim.x) {
        const int e0 = tile * E_TILE;
        const int nE = min(E_TILE, n_edges - e0);

        // cooperative load: rbf -> duplicated float2 in smem
        for (int i = tid; i < nE * K_PAD; i += 128) {
            int e = i / K_PAD;
            int k = i - e * K_PAD;
            float v = (k < N_RBF) ? rbf[(size_t)(e0 + e) * N_RBF + k] : 0.f;
            rr_sh[e][k] = make_float2(v, v);
        }
        if (tid < nE) {
            float dd = dist[e0 + tid];
            float w  = 0.5f * (__cosf(dd * PI_OVER_CUTOFF) + 1.0f);
            w_sh[tid]   = (dd < CUTOFF_F) ? w : 0.f;
            typ_sh[tid] = node_type[src[e0 + tid]];
            dst_sh[tid] = dst[e0 + tid];
        }
        __syncthreads();

        // group g processes edges e = g, g+2, ...
        for (int e = g; e < nE; e += 2) {
            unsigned long long accA = 0ull, accB = 0ull;
            const ulonglong2* rp = (const ulonglong2*)&rr_sh[e][0];
#pragma unroll
            for (int kk = 0; kk < K_PAD / 2; kk++) {
                ulonglong2 rv = rp[kk];           // LDS.128: (r_k,r_k,r_{k+1},r_{k+1})
                accA = ffma2(rv.x, wreg2[2 * kk],     accA);
                accB = ffma2(rv.y, wreg2[2 * kk + 1], accB);
            }
            float lo, hi;
            unpack2(fadd2(accA, accB), lo, hi);
            float w  = w_sh[e];
            float2 em = *(const float2*)&emb[(size_t)typ_sh[e] * D_DIM + d0];
            float m0 = em.x * (lo + be0) * w;
            float m1 = em.y * (hi + be1) * w;
            *(float2*)&msg_sh[e][d0] = make_float2(m0, m1);
        }
        __syncthreads();

        // vectorized scatter: warp w handles edges w, w+4, ...
        const int warp = tid >> 5, lane = tid & 31;
        for (int e = warp; e < nE; e += 4) {
            float4 v = *(const float4*)&msg_sh[e][lane * 4];
            atomicAdd((float4*)&g_acc[(size_t)dst_sh[e] * D_DIM + lane * 4], v);
        }
        __syncthreads();
    }
}

// ---------------------------------------------------------------------------
// Kernel 3: out = x_nodes @ Wc[:, :128].T + g_acc @ Wc[:, 128:].T + b_c
//   FFMA2 version: both operands are j-contiguous -> no packing needed.
//   256 threads: tid = h*128 + d.  NT=16 node register blocking.
//   W_c transposed in smem with stride 132 (conflict-free LDS.128 phases).
// ---------------------------------------------------------------------------
#define NT 16
#define W_STRIDE 132

__global__ void __launch_bounds__(256) out_kernel(
    const float* __restrict__ x_nodes,  // [N, 128]
    const float* __restrict__ W_c,      // [128, 256]
    const float* __restrict__ b_c,      // [128]
    float* __restrict__ out,            // [N, 128]
    int n_nodes)
{
    extern __shared__ float sh[];
    float* w_sh  = sh;                           // 256 * 132
    float* x_sh  = w_sh + 256 * W_STRIDE;        // NT * 256
    float* ps_sh = x_sh + NT * 256;              // NT * 128

    const int tid = threadIdx.x;
    const int h   = tid >> 7;        // j-half (0: x_nodes, 1: g_acc)
    const int d   = tid & 127;       // output dim

    // load + transpose W_c: row (h*128+d) holds W_c[d][h*128 .. h*128+127]
    for (int i = tid; i < 128 * 256; i += 256) {
        int dd = i >> 8;
        int j  = i & 255;
        w_sh[((j >> 7) * 128 + dd) * W_STRIDE + (j & 127)] = W_c[i];
    }
    const float bcv = b_c[d];
    __syncthreads();

    const float* wrow = &w_sh[tid * W_STRIDE];
    const int num_tiles = (n_nodes + NT - 1) / NT;

    for (int t = blockIdx.x; t < num_tiles; t += gridDim.x) {
        const int n0 = t * NT;
        const int nN = min(NT, n_nodes - n0);

        // stage x tile: row n = [x_nodes[n0+n] | g_acc[n0+n]], 256 floats
        for (int i = tid; i < nN * 64; i += 256) {
            int n = i >> 6, q = i & 63;
            float4 v;
            if (q < 32) v = *(const float4*)&x_nodes[(size_t)(n0 + n) * 128 + q * 4];
            else        v = *(const float4*)&g_acc [(size_t)(n0 + n) * 128 + (q - 32) * 4];
            *(float4*)&x_sh[n * 256 + q * 4] = v;
        }
        __syncthreads();

        unsigned long long acc2[NT];
#pragma unroll
        for (int n = 0; n < NT; n++) acc2[n] = 0ull;

        const float* xbase = x_sh + h * 128;
#pragma unroll
        for (int jq = 0; jq < 32; jq++) {
            ulonglong2 w2 = *(const ulonglong2*)&wrow[jq * 4];
#pragma unroll
            for (int n = 0; n < NT; n++) {
                ulonglong2 x2 = *(const ulonglong2*)&xbase[n * 256 + jq * 4];
                acc2[n] = ffma2(x2.x, w2.x, acc2[n]);
                acc2[n] = ffma2(x2.y, w2.y, acc2[n]);
            }
        }

        // reduce pairs and combine halves
        if (h == 1) {
#pragma unroll
            for (int n = 0; n < NT; n++) {
                float lo, hi;
                unpack2(acc2[n], lo, hi);
                ps_sh[n * 128 + d] = lo + hi;
            }
        }
        __syncthreads();
        if (h == 0) {
            for (int n = 0; n < nN; n++) {
                float lo, hi;
                unpack2(acc2[n], lo, hi);
                out[(size_t)(n0 + n) * 128 + d] = (lo + hi) + ps_sh[n * 128 + d] + bcv;
            }
        }
        __syncthreads();
    }
}

// ---------------------------------------------------------------------------
// Launch
// ---------------------------------------------------------------------------
extern "C" void kernel_launch(void* const* d_in, const int* in_sizes, int n_in,
                              void* d_out, int out_size)
{
    const int*   node_type = (const int*)  d_in[0];
    const float* x_nodes   = (const float*)d_in[1];
    const int*   src       = (const int*)  d_in[2];
    const int*   dst       = (const int*)  d_in[3];
    const float* rbf       = (const float*)d_in[4];
    const float* dist      = (const float*)d_in[5];
    const float* emb       = (const float*)d_in[6];
    const float* W_e       = (const float*)d_in[7];
    const float* b_e       = (const float*)d_in[8];
    const float* W_c       = (const float*)d_in[9];
    const float* b_c       = (const float*)d_in[10];
    float* out = (float*)d_out;

    const int n_nodes = in_sizes[0];
    const int n_edges = in_sizes[2];

    // 1) zero accumulator
    int n4 = n_nodes * D_DIM / 4;
    zero_kernel<<<(n4 + 255) / 256, 256>>>(n4);

    // 2) edge projection + gather-multiply-scatter
    edge_kernel<<<760, 128>>>(rbf, dist, src, dst, node_type, emb, W_e, b_e, n_edges);

    // 3) final combine GEMM
    size_t shmem = (256 * W_STRIDE + NT * 256 + NT * 128) * sizeof(float);
    cudaFuncSetAttribute(out_kernel, cudaFuncAttributeMaxDynamicSharedMemorySize, (int)shmem);
    out_kernel<<<152, 256, shmem>>>(x_nodes, W_c, b_c, out, n_nodes);
}

// round 5
// speedup vs baseline: 1.6404x; 1.6404x over previous
#include <cuda_runtime.h>
#include <cuda_bf16.h>

#define D_DIM     128
#define N_RBF     50
#define K_PAD     52            // pad to multiple of 4 for float4 LDS
#define E_TILE    32            // edges per tile in edge kernel
#define MAX_NODES 50000
#define CUTOFF_F  5.0f
#define PI_OVER_CUTOFF 0.62831853071795864769f

// scatter-sum accumulator (device global scratch; no cudaMalloc allowed)
__device__ float g_acc[(size_t)MAX_NODES * D_DIM];

// ---------------------------------------------------------------------------
// Kernel 1: zero a float4 buffer
// ---------------------------------------------------------------------------
__global__ void zero_kernel(float4* p, int n4) {
    int i = blockIdx.x * blockDim.x + threadIdx.x;
    if (i < n4) p[i] = make_float4(0.f, 0.f, 0.f, 0.f);
}

// ---------------------------------------------------------------------------
// Kernel 2: edge kernel (proven R2 version).
//   Thread d (0..127) owns output dim d; W_e[d,0:50] in 52 registers.
//   rbf tile staged in smem, broadcast LDS.128 reads.
//   msg staged in smem, scattered with vectorized float4 atomicAdd.
// ---------------------------------------------------------------------------
__global__ void __launch_bounds__(128) edge_kernel(
    const float* __restrict__ rbf,       // [E, 50]
    const float* __restrict__ dist,      // [E]
    const int*   __restrict__ src,       // [E]
    const int*   __restrict__ dst,       // [E]
    const int*   __restrict__ node_type, // [N]
    const float* __restrict__ emb,       // [100, 128]
    const float* __restrict__ W_e,       // [128, 50]
    const float* __restrict__ b_e,       // [128]
    int n_edges)
{
    __shared__ float rbf_sh[E_TILE][K_PAD];
    __shared__ float msg_sh[E_TILE][D_DIM];
    __shared__ float w_sh[E_TILE];
    __shared__ int   dst_sh[E_TILE];
    __shared__ int   typ_sh[E_TILE];

    const int tid = threadIdx.x;
    const int d   = tid;

    float wreg[K_PAD];
#pragma unroll
    for (int k = 0; k < N_RBF; k++) wreg[k] = W_e[d * N_RBF + k];
#pragma unroll
    for (int k = N_RBF; k < K_PAD; k++) wreg[k] = 0.f;
    const float be = b_e[d];

    const int num_tiles = (n_edges + E_TILE - 1) / E_TILE;
    for (int tile = blockIdx.x; tile < num_tiles; tile += gridDim.x) {
        const int e0 = tile * E_TILE;
        const int nE = min(E_TILE, n_edges - e0);

        for (int i = tid; i < nE * N_RBF; i += blockDim.x) {
            int e = i / N_RBF;
            int k = i - e * N_RBF;
            rbf_sh[e][k] = rbf[(size_t)e0 * N_RBF + i];
        }
        if (tid < E_TILE) {
            rbf_sh[tid][N_RBF]     = 0.f;
            rbf_sh[tid][N_RBF + 1] = 0.f;
        }
        if (tid < nE) {
            float dd = dist[e0 + tid];
            float w  = 0.5f * (__cosf(dd * PI_OVER_CUTOFF) + 1.0f);
            w_sh[tid]   = (dd < CUTOFF_F) ? w : 0.f;
            typ_sh[tid] = node_type[src[e0 + tid]];
            dst_sh[tid] = dst[e0 + tid];
        }
        __syncthreads();

        for (int e = 0; e < nE; e++) {
            float a0 = 0.f, a1 = 0.f, a2 = 0.f, a3 = 0.f;
#pragma unroll
            for (int k = 0; k < K_PAD; k += 4) {
                float4 r = *(const float4*)&rbf_sh[e][k];
                a0 = fmaf(r.x, wreg[k],     a0);
                a1 = fmaf(r.y, wreg[k + 1], a1);
                a2 = fmaf(r.z, wreg[k + 2], a2);
                a3 = fmaf(r.w, wreg[k + 3], a3);
            }
            float xe = (a0 + a1) + (a2 + a3) + be;
            float m  = __ldg(&emb[(size_t)typ_sh[e] * D_DIM + d]) * xe * w_sh[e];
            msg_sh[e][d] = m;
        }
        __syncthreads();

        const int warp = tid >> 5, lane = tid & 31;
        for (int e = warp; e < nE; e += 4) {
            float4 v = *(const float4*)&msg_sh[e][lane * 4];
            atomicAdd((float4*)&g_acc[(size_t)dst_sh[e] * D_DIM + lane * 4], v);
        }
        __syncthreads();
    }
}

// ---------------------------------------------------------------------------
// Kernel 3: out += xhalf @ Wc_half.T  (half-j per block, combine via atomics)
//   h = blockIdx.x & 1 selects the j-half: 0 -> x_nodes (adds b_c), 1 -> g_acc.
//   128 threads, thread owns output dim d. W half transposed into smem
//   (68 KB -> 2 blocks/SM). NT=16 node register blocking.
//   Result tile staged in smem, combined into zero-initialized out with
//   float4 atomicAdd (RED.E.128).
// ---------------------------------------------------------------------------
#define NT 16
#define W_STRIDE 132

__global__ void __launch_bounds__(128) out_kernel(
    const float* __restrict__ x_nodes,  // [N, 128]
    const float* __restrict__ W_c,      // [128, 256]
    const float* __restrict__ b_c,      // [128]
    float* __restrict__ out,            // [N, 128]
    int n_nodes)
{
    extern __shared__ float sh[];
    float* w_sh   = sh;                          // 128 * 132
    float* x_sh   = w_sh + 128 * W_STRIDE;       // NT * 128
    float* res_sh = x_sh + NT * 128;             // NT * 128

    const int tid = threadIdx.x;                 // == output dim d
    const int h   = blockIdx.x & 1;              // j-half
    const float* xsrc = h ? g_acc : x_nodes;

    // load + transpose this half of W_c: w_sh[d][j] = W_c[d][h*128 + j]
    for (int i = tid; i < 128 * 128; i += 128) {
        int dd = i >> 7;
        int j  = i & 127;
        w_sh[dd * W_STRIDE + j] = W_c[dd * 256 + h * 128 + j];
    }
    const float bcv = h ? 0.f : b_c[tid];
    __syncthreads();

    const float* wrow = &w_sh[tid * W_STRIDE];
    const int num_tiles = (n_nodes + NT - 1) / NT;
    const int bstride = gridDim.x >> 1;

    for (int t = (blockIdx.x >> 1); t < num_tiles; t += bstride) {
        const int n0 = t * NT;
        const int nN = min(NT, n_nodes - n0);

        // stage x tile: NT rows x 128 floats
        for (int i = tid; i < nN * 32; i += 128) {
            int n = i >> 5, q = i & 31;
            *(float4*)&x_sh[n * 128 + q * 4] =
                *(const float4*)&xsrc[(size_t)(n0 + n) * 128 + q * 4];
        }
        __syncthreads();

        float acc[NT];
#pragma unroll
        for (int n = 0; n < NT; n++) acc[n] = 0.f;

#pragma unroll
        for (int jq = 0; jq < 32; jq++) {
            float4 w = *(const float4*)&wrow[jq * 4];
#pragma unroll
            for (int n = 0; n < NT; n++) {
                float4 x = *(const float4*)&x_sh[n * 128 + jq * 4];
                acc[n] = fmaf(x.w, w.w,
                         fmaf(x.z, w.z,
                         fmaf(x.y, w.y,
                         fmaf(x.x, w.x, acc[n]))));
            }
        }

        // stage result tile, then vectorized atomic combine into out
#pragma unroll
        for (int n = 0; n < NT; n++) res_sh[n * 128 + tid] = acc[n] + bcv;
        __syncthreads();

        const int warp = tid >> 5, lane = tid & 31;
        for (int n = warp; n < nN; n += 4) {
            float4 v = *(const float4*)&res_sh[n * 128 + lane * 4];
            atomicAdd((float4*)&out[(size_t)(n0 + n) * 128 + lane * 4], v);
        }
        __syncthreads();
    }
}

// ---------------------------------------------------------------------------
// Launch
// ---------------------------------------------------------------------------
extern "C" void kernel_launch(void* const* d_in, const int* in_sizes, int n_in,
                              void* d_out, int out_size)
{
    const int*   node_type = (const int*)  d_in[0];
    const float* x_nodes   = (const float*)d_in[1];
    const int*   src       = (const int*)  d_in[2];
    const int*   dst       = (const int*)  d_in[3];
    const float* rbf       = (const float*)d_in[4];
    const float* dist      = (const float*)d_in[5];
    const float* emb       = (const float*)d_in[6];
    const float* W_e       = (const float*)d_in[7];
    const float* b_e       = (const float*)d_in[8];
    const float* W_c       = (const float*)d_in[9];
    const float* b_c       = (const float*)d_in[10];
    float* out = (float*)d_out;

    const int n_nodes = in_sizes[0];
    const int n_edges = in_sizes[2];

    // 1) zero accumulator and output (output combined via atomics)
    float* g_acc_ptr = nullptr;
    cudaGetSymbolAddress((void**)&g_acc_ptr, g_acc);
    int n4 = n_nodes * D_DIM / 4;
    zero_kernel<<<(n4 + 255) / 256, 256>>>((float4*)g_acc_ptr, n4);
    zero_kernel<<<(n4 + 255) / 256, 256>>>((float4*)out, n4);

    // 2) edge projection + gather-multiply-scatter
    edge_kernel<<<760, 128>>>(rbf, dist, src, dst, node_type, emb, W_e, b_e, n_edges);

    // 3) final combine GEMM (half-j per block)
    size_t shmem = (128 * W_STRIDE + 2 * NT * 128) * sizeof(float);
    cudaFuncSetAttribute(out_kernel, cudaFuncAttributeMaxDynamicSharedMemorySize, (int)shmem);
    out_kernel<<<592, 128, shmem>>>(x_nodes, W_c, b_c, out, n_nodes);
}

// round 9
// speedup vs baseline: 2.0515x; 1.2506x over previous
#include <cuda_runtime.h>
#include <cuda_bf16.h>

#define D_DIM     128
#define N_RBF     50
#define K_PAD     52            // pad to multiple of 4 for float4 LDS
#define E_TILE    32            // edges per tile in edge kernel
#define MAX_NODES 50000
#define CUTOFF_F  5.0f
#define PI_OVER_CUTOFF 0.62831853071795864769f

// scatter-sum accumulator (device global scratch; no cudaMalloc allowed)
__device__ float g_acc[(size_t)MAX_NODES * D_DIM];

// ---------------------------------------------------------------------------
// Kernel 1: zero both accumulator and output in one pass
// ---------------------------------------------------------------------------
__global__ void zero2_kernel(float4* a, float4* b, int n4) {
    int i = blockIdx.x * blockDim.x + threadIdx.x;
    if (i < n4) {
        a[i] = make_float4(0.f, 0.f, 0.f, 0.f);
        b[i] = make_float4(0.f, 0.f, 0.f, 0.f);
    }
}

// ---------------------------------------------------------------------------
// Kernel 2: edge kernel, double-buffered.
//   Thread d owns output dim d; W_e[d,:] in 52 registers.
//   While computing tile t from buf p, tile t+stride is loaded into buf p^1
//   (global->smem overlapped with the ~3300-cycle FMA phase).
//   2 barriers per tile. msg staged in smem, scattered with float4 atomicAdd.
// ---------------------------------------------------------------------------
__global__ void __launch_bounds__(128) edge_kernel(
    const float* __restrict__ rbf,       // [E, 50]
    const float* __restrict__ dist,      // [E]
    const int*   __restrict__ src,       // [E]
    const int*   __restrict__ dst,       // [E]
    const int*   __restrict__ node_type, // [N]
    const float* __restrict__ emb,       // [100, 128]
    const float* __restrict__ W_e,       // [128, 50]
    const float* __restrict__ b_e,       // [128]
    int n_edges)
{
    __shared__ float rbf_sh[2][E_TILE][K_PAD];
    __shared__ float msg_sh[E_TILE][D_DIM];
    __shared__ float w_sh[2][E_TILE];
    __shared__ int   dst_sh[2][E_TILE];
    __shared__ int   typ_sh[2][E_TILE];

    const int tid = threadIdx.x;
    const int d   = tid;

    float wreg[K_PAD];
#pragma unroll
    for (int k = 0; k < N_RBF; k++) wreg[k] = W_e[d * N_RBF + k];
#pragma unroll
    for (int k = N_RBF; k < K_PAD; k++) wreg[k] = 0.f;
    const float be = b_e[d];

    const int num_tiles = (n_edges + E_TILE - 1) / E_TILE;

    // tile loader (no barrier inside)
    auto load_tile = [&](int t, int b) {
        const int e0 = t * E_TILE;
        const int nE = min(E_TILE, n_edges - e0);
        for (int i = tid; i < nE * N_RBF; i += 128) {
            int e = i / N_RBF;
            int k = i - e * N_RBF;
            rbf_sh[b][e][k] = rbf[(size_t)e0 * N_RBF + i];
        }
        if (tid < E_TILE) {
            rbf_sh[b][tid][N_RBF]     = 0.f;
            rbf_sh[b][tid][N_RBF + 1] = 0.f;
        }
        if (tid < nE) {
            float dd = dist[e0 + tid];
            float w  = 0.5f * (__cosf(dd * PI_OVER_CUTOFF) + 1.0f);
            w_sh[b][tid]   = (dd < CUTOFF_F) ? w : 0.f;
            typ_sh[b][tid] = node_type[src[e0 + tid]];
            dst_sh[b][tid] = dst[e0 + tid];
        }
    };

    int p = 0;
    if (blockIdx.x < num_tiles) load_tile(blockIdx.x, 0);

    for (int tile = blockIdx.x; tile < num_tiles; tile += gridDim.x) {
        const int nE = min(E_TILE, n_edges - tile * E_TILE);

        __syncthreads();                 // buf[p] filled; msg_sh free

        const int next = tile + gridDim.x;
        if (next < num_tiles) load_tile(next, p ^ 1);   // overlap with compute

        for (int e = 0; e < nE; e++) {
            float a0 = 0.f, a1 = 0.f, a2 = 0.f, a3 = 0.f;
#pragma unroll
            for (int k = 0; k < K_PAD; k += 4) {
                float4 r = *(const float4*)&rbf_sh[p][e][k];
                a0 = fmaf(r.x, wreg[k],     a0);
                a1 = fmaf(r.y, wreg[k + 1], a1);
                a2 = fmaf(r.z, wreg[k + 2], a2);
                a3 = fmaf(r.w, wreg[k + 3], a3);
            }
            float xe = (a0 + a1) + (a2 + a3) + be;
            float m  = __ldg(&emb[(size_t)typ_sh[p][e] * D_DIM + d]) * xe * w_sh[p][e];
            msg_sh[e][d] = m;
        }
        __syncthreads();                 // msg_sh ready

        const int warp = tid >> 5, lane = tid & 31;
        for (int e = warp; e < nE; e += 4) {
            float4 v = *(const float4*)&msg_sh[e][lane * 4];
            atomicAdd((float4*)&g_acc[(size_t)dst_sh[p][e] * D_DIM + lane * 4], v);
        }
        p ^= 1;
    }
}

// ---------------------------------------------------------------------------
// Kernel 3: out += xhalf @ Wc_half.T  (half-j per block, DT=2 dim blocking)
//   h = blockIdx.x & 1 selects the j-half source (0: x_nodes + bias, 1: g_acc).
//   128 threads: nh = t>>6 picks the node sub-group (16 of 32 tile nodes),
//   dl = t&63: thread owns dims dl and dl+64.
//   Per jq: 2 w-LDS.128 + 16 x-LDS.128 (broadcast) per 128 FFMA.
//   W half transposed in smem, stride 132 (conflict-free phases; +64 rows
//   shift banks by 0 mod 32). Result tile staged, combined via float4 atomics.
// ---------------------------------------------------------------------------
#define NT_OUT 32          // nodes per block tile
#define W_STRIDE 132

__global__ void __launch_bounds__(128) out_kernel(
    const float* __restrict__ x_nodes,  // [N, 128]
    const float* __restrict__ W_c,      // [128, 256]
    const float* __restrict__ b_c,      // [128]
    float* __restrict__ out,            // [N, 128]
    int n_nodes)
{
    extern __shared__ float sh[];
    float* w_sh   = sh;                          // 128 * 132
    float* x_sh   = w_sh + 128 * W_STRIDE;       // NT_OUT * 128
    float* res_sh = x_sh + NT_OUT * 128;         // NT_OUT * 128

    const int tid = threadIdx.x;
    const int nh  = tid >> 6;        // node sub-group (0..1)
    const int dl  = tid & 63;        // dim pair: dl, dl+64
    const int h   = blockIdx.x & 1;  // j-half
    const float* xsrc = h ? g_acc : x_nodes;

    // load + transpose this half of W_c: w_sh[d][j] = W_c[d][h*128 + j]
    for (int i = tid; i < 128 * 128; i += 128) {
        int dd = i >> 7;
        int j  = i & 127;
        w_sh[dd * W_STRIDE + j] = W_c[dd * 256 + h * 128 + j];
    }
    const float bc0 = h ? 0.f : b_c[dl];
    const float bc1 = h ? 0.f : b_c[dl + 64];
    __syncthreads();

    const float* wrow0 = &w_sh[dl * W_STRIDE];
    const float* wrow1 = &w_sh[(dl + 64) * W_STRIDE];
    const int num_tiles = (n_nodes + NT_OUT - 1) / NT_OUT;
    const int bstride = gridDim.x >> 1;

    for (int t = (blockIdx.x >> 1); t < num_tiles; t += bstride) {
        const int n0 = t * NT_OUT;
        const int nN = min(NT_OUT, n_nodes - n0);

        // stage x tile: nN rows x 128 floats
        for (int i = tid; i < nN * 32; i += 128) {
            int n = i >> 5, q = i & 31;
            *(float4*)&x_sh[n * 128 + q * 4] =
                *(const float4*)&xsrc[(size_t)(n0 + n) * 128 + q * 4];
        }
        __syncthreads();

        float acc0[16], acc1[16];
#pragma unroll
        for (int n = 0; n < 16; n++) { acc0[n] = 0.f; acc1[n] = 0.f; }

        const float* xbase = &x_sh[nh * 16 * 128];
#pragma unroll
        for (int jq = 0; jq < 32; jq++) {
            float4 w0 = *(const float4*)&wrow0[jq * 4];
            float4 w1 = *(const float4*)&wrow1[jq * 4];
#pragma unroll
            for (int n = 0; n < 16; n++) {
                float4 x = *(const float4*)&xbase[n * 128 + jq * 4];
                acc0[n] = fmaf(x.w, w0.w, fmaf(x.z, w0.z,
                          fmaf(x.y, w0.y, fmaf(x.x, w0.x, acc0[n]))));
                acc1[n] = fmaf(x.w, w1.w, fmaf(x.z, w1.z,
                          fmaf(x.y, w1.y, fmaf(x.x, w1.x, acc1[n]))));
            }
        }

        // stage result tile (conflict-free scalar STS), then atomic combine
#pragma unroll
        for (int n = 0; n < 16; n++) {
            res_sh[(nh * 16 + n) * 128 + dl]      = acc0[n] + bc0;
            res_sh[(nh * 16 + n) * 128 + dl + 64] = acc1[n] + bc1;
        }
        __syncthreads();

        const int warp = tid >> 5, lane = tid & 31;
        for (int n = warp; n < nN; n += 4) {
            float4 v = *(const float4*)&res_sh[n * 128 + lane * 4];
            atomicAdd((float4*)&out[(size_t)(n0 + n) * 128 + lane * 4], v);
        }
        __syncthreads();
    }
}

// ---------------------------------------------------------------------------
// Launch
// ---------------------------------------------------------------------------
extern "C" void kernel_launch(void* const* d_in, const int* in_sizes, int n_in,
                              void* d_out, int out_size)
{
    const int*   node_type = (const int*)  d_in[0];
    const float* x_nodes   = (const float*)d_in[1];
    const int*   src       = (const int*)  d_in[2];
    const int*   dst       = (const int*)  d_in[3];
    const float* rbf       = (const float*)d_in[4];
    const float* dist      = (const float*)d_in[5];
    const float* emb       = (const float*)d_in[6];
    const float* W_e       = (const float*)d_in[7];
    const float* b_e       = (const float*)d_in[8];
    const float* W_c       = (const float*)d_in[9];
    const float* b_c       = (const float*)d_in[10];
    float* out = (float*)d_out;

    const int n_nodes = in_sizes[0];
    const int n_edges = in_sizes[2];

    // 1) zero accumulator and output together
    float* g_acc_ptr = nullptr;
    cudaGetSymbolAddress((void**)&g_acc_ptr, g_acc);
    int n4 = n_nodes * D_DIM / 4;
    zero2_kernel<<<(n4 + 255) / 256, 256>>>((float4*)g_acc_ptr, (float4*)out, n4);

    // 2) edge projection + gather-multiply-scatter (double-buffered)
    edge_kernel<<<888, 128>>>(rbf, dist, src, dst, node_type, emb, W_e, b_e, n_edges);

    // 3) final combine GEMM (half-j per block, DT=2)
    size_t shmem = (128 * W_STRIDE + 2 * NT_OUT * 128) * sizeof(float);
    cudaFuncSetAttribute(out_kernel, cudaFuncAttributeMaxDynamicSharedMemorySize, (int)shmem);
    out_kernel<<<296, 128, shmem>>>(x_nodes, W_c, b_c, out, n_nodes);
}

// round 11
// speedup vs baseline: 2.6997x; 1.3160x over previous
#include <cuda_runtime.h>
#include <cuda_bf16.h>

#define D_DIM     128
#define N_RBF     50
#define KP        56            // MMA K padded to 7 x 8
#define E_TILE    32            // edges per tile
#define RBF_STRIDE 60           // conflict-free B-fragment banks
#define MSG_STRIDE 132          // conflict-free epilogue STS; 528B = 33*16 aligned
#define MAX_NODES 50000
#define CUTOFF_F  5.0f
#define PI_OVER_CUTOFF 0.62831853071795864769f

// scatter-sum accumulator (device global scratch; no cudaMalloc allowed)
__device__ float g_acc[(size_t)MAX_NODES * D_DIM];

// ---------------------------------------------------------------------------
// helpers
// ---------------------------------------------------------------------------
__device__ __forceinline__ unsigned cvt_tf32(float x) {
    unsigned r;
    asm("cvt.rna.tf32.f32 %0, %1;" : "=r"(r) : "f"(x));
    return r;
}
__device__ __forceinline__ void mma_tf32(float* acc, const unsigned* a,
                                         unsigned b0, unsigned b1) {
    asm("mma.sync.aligned.m16n8k8.row.col.f32.tf32.tf32.f32 "
        "{%0,%1,%2,%3},{%4,%5,%6,%7},{%8,%9},{%0,%1,%2,%3};"
        : "+f"(acc[0]), "+f"(acc[1]), "+f"(acc[2]), "+f"(acc[3])
        : "r"(a[0]), "r"(a[1]), "r"(a[2]), "r"(a[3]), "r"(b0), "r"(b1));
}

// ---------------------------------------------------------------------------
// Kernel 1: zero both accumulator and output in one pass
// ---------------------------------------------------------------------------
__global__ void zero2_kernel(float4* a, float4* b, int n4) {
    int i = blockIdx.x * blockDim.x + threadIdx.x;
    if (i < n4) {
        a[i] = make_float4(0.f, 0.f, 0.f, 0.f);
        b[i] = make_float4(0.f, 0.f, 0.f, 0.f);
    }
}

// ---------------------------------------------------------------------------
// Kernel 2: edge kernel, TF32 tensor-core version, double-buffered.
//   C[dim, edge] = W_e(A, in 56 regs as tf32) x rbf_tile(B, smem tf32).
//   Warp w owns dims [32w, 32w+32) for all 32 tile edges:
//   2 m-tiles x 4 n-tiles x 7 k-steps of m16n8k8.
//   Epilogue (fp32): (acc + b_e) * emb[type] * cutoff -> msg_sh -> float4 atomicAdd.
// ---------------------------------------------------------------------------
__global__ void __launch_bounds__(128) edge_kernel(
    const float* __restrict__ rbf,       // [E, 50]
    const float* __restrict__ dist,      // [E]
    const int*   __restrict__ src,       // [E]
    const int*   __restrict__ dst,       // [E]
    const int*   __restrict__ node_type, // [N]
    const float* __restrict__ emb,       // [100, 128]
    const float* __restrict__ W_e,       // [128, 50]
    const float* __restrict__ b_e,       // [128]
    int n_edges)
{
    __shared__ unsigned rbf_sh[2][E_TILE][RBF_STRIDE];  // tf32 bit patterns
    __shared__ float    msg_sh[E_TILE][MSG_STRIDE];
    __shared__ float    w_sh[2][E_TILE];
    __shared__ int      dst_sh[2][E_TILE];
    __shared__ int      typ_sh[2][E_TILE];

    const int tid  = threadIdx.x;
    const int warp = tid >> 5;
    const int lane = tid & 31;
    const int g4   = lane >> 2;      // groupID (rows)
    const int t4   = lane & 3;       // thread-in-group (cols)
    const int wbase = warp * 32;     // dim base for this warp

    // A fragments: W_e as tf32, loaded once. a_frag[mt][ks][j]
    unsigned a_frag[2][7][4];
#pragma unroll
    for (int mt = 0; mt < 2; mt++)
#pragma unroll
        for (int ks = 0; ks < 7; ks++)
#pragma unroll
            for (int j = 0; j < 4; j++) {
                int d = wbase + mt * 16 + g4 + ((j & 1) ? 8 : 0);
                int k = ks * 8 + t4 + ((j >= 2) ? 4 : 0);
                float v = (k < N_RBF) ? W_e[d * N_RBF + k] : 0.f;
                a_frag[mt][ks][j] = cvt_tf32(v);
            }
    // bias registers for this thread's 4 dim rows
    float be00 = b_e[wbase + g4];
    float be01 = b_e[wbase + g4 + 8];
    float be10 = b_e[wbase + 16 + g4];
    float be11 = b_e[wbase + 16 + g4 + 8];

    const int num_tiles = (n_edges + E_TILE - 1) / E_TILE;

    auto load_tile = [&](int t, int b) {
        const int e0 = t * E_TILE;
        const int nE = min(E_TILE, n_edges - e0);
        for (int i = tid; i < E_TILE * KP; i += 128) {
            int e = i / KP;
            int k = i - e * KP;
            float v = (k < N_RBF && e < nE) ? rbf[(size_t)(e0 + e) * N_RBF + k] : 0.f;
            rbf_sh[b][e][k] = cvt_tf32(v);
        }
        if (tid < E_TILE) {
            bool valid = tid < nE;
            float dd = valid ? dist[e0 + tid] : 1e9f;
            float w  = 0.5f * (__cosf(dd * PI_OVER_CUTOFF) + 1.0f);
            w_sh[b][tid]   = (dd < CUTOFF_F) ? w : 0.f;
            typ_sh[b][tid] = valid ? node_type[src[e0 + tid]] : 0;
            dst_sh[b][tid] = valid ? dst[e0 + tid] : 0;
        }
    };

    int p = 0;
    if (blockIdx.x < num_tiles) load_tile(blockIdx.x, 0);

    for (int tile = blockIdx.x; tile < num_tiles; tile += gridDim.x) {
        const int nE = min(E_TILE, n_edges - tile * E_TILE);

        __syncthreads();                 // buf[p] ready; msg_sh free

        const int next = tile + gridDim.x;
        if (next < num_tiles) load_tile(next, p ^ 1);   // overlap with MMA

        float acc[2][4][4];
#pragma unroll
        for (int mt = 0; mt < 2; mt++)
#pragma unroll
            for (int nt = 0; nt < 4; nt++)
#pragma unroll
                for (int j = 0; j < 4; j++) acc[mt][nt][j] = 0.f;

        // process n-tiles in pairs: 4 independent MMA chains per k-step
#pragma unroll
        for (int ntp = 0; ntp < 2; ntp++) {
            unsigned bfr[2][7][2];
#pragma unroll
            for (int ntl = 0; ntl < 2; ntl++) {
                int e = (ntp * 2 + ntl) * 8 + g4;
#pragma unroll
                for (int ks = 0; ks < 7; ks++) {
                    bfr[ntl][ks][0] = rbf_sh[p][e][ks * 8 + t4];
                    bfr[ntl][ks][1] = rbf_sh[p][e][ks * 8 + t4 + 4];
                }
            }
#pragma unroll
            for (int ks = 0; ks < 7; ks++)
#pragma unroll
                for (int mt = 0; mt < 2; mt++)
#pragma unroll
                    for (int ntl = 0; ntl < 2; ntl++)
                        mma_tf32(acc[mt][ntp * 2 + ntl], a_frag[mt][ks],
                                 bfr[ntl][ks][0], bfr[ntl][ks][1]);
        }

        // epilogue: msg = emb[type] * (acc + b_e) * cutoff  (fp32)
#pragma unroll
        for (int mt = 0; mt < 2; mt++) {
            const int d0 = wbase + mt * 16 + g4;
            const int d1 = d0 + 8;
            const float beA = mt ? be10 : be00;
            const float beB = mt ? be11 : be01;
#pragma unroll
            for (int nt = 0; nt < 4; nt++) {
                const int e0 = nt * 8 + 2 * t4;
                const int e1 = e0 + 1;
                const float w0 = w_sh[p][e0], w1 = w_sh[p][e1];
                const int  ty0 = typ_sh[p][e0], ty1 = typ_sh[p][e1];
                float em00 = __ldg(&emb[(size_t)ty0 * D_DIM + d0]);
                float em10 = __ldg(&emb[(size_t)ty1 * D_DIM + d0]);
                float em01 = __ldg(&emb[(size_t)ty0 * D_DIM + d1]);
                float em11 = __ldg(&emb[(size_t)ty1 * D_DIM + d1]);
                msg_sh[e0][d0] = em00 * (acc[mt][nt][0] + beA) * w0;
                msg_sh[e1][d0] = em10 * (acc[mt][nt][1] + beA) * w1;
                msg_sh[e0][d1] = em01 * (acc[mt][nt][2] + beB) * w0;
                msg_sh[e1][d1] = em11 * (acc[mt][nt][3] + beB) * w1;
            }
        }
        __syncthreads();                 // msg_sh ready

        for (int e = warp; e < nE; e += 4) {
            float4 v = *(const float4*)&msg_sh[e][lane * 4];
            atomicAdd((float4*)&g_acc[(size_t)dst_sh[p][e] * D_DIM + lane * 4], v);
        }
        p ^= 1;
    }
}

// ---------------------------------------------------------------------------
// Kernel 3: out += xhalf @ Wc_half.T  (half-j per block, DT=2 dim blocking)
//   (unchanged from R9 — proven ~100us)
// ---------------------------------------------------------------------------
#define NT_OUT 32
#define W_STRIDE 132

__global__ void __launch_bounds__(128) out_kernel(
    const float* __restrict__ x_nodes,  // [N, 128]
    const float* __restrict__ W_c,      // [128, 256]
    const float* __restrict__ b_c,      // [128]
    float* __restrict__ out,            // [N, 128]
    int n_nodes)
{
    extern __shared__ float sh[];
    float* w_sh   = sh;                          // 128 * 132
    float* x_sh   = w_sh + 128 * W_STRIDE;       // NT_OUT * 128
    float* res_sh = x_sh + NT_OUT * 128;         // NT_OUT * 128

    const int tid = threadIdx.x;
    const int nh  = tid >> 6;
    const int dl  = tid & 63;
    const int h   = blockIdx.x & 1;
    const float* xsrc = h ? g_acc : x_nodes;

    for (int i = tid; i < 128 * 128; i += 128) {
        int dd = i >> 7;
        int j  = i & 127;
        w_sh[dd * W_STRIDE + j] = W_c[dd * 256 + h * 128 + j];
    }
    const float bc0 = h ? 0.f : b_c[dl];
    const float bc1 = h ? 0.f : b_c[dl + 64];
    __syncthreads();

    const float* wrow0 = &w_sh[dl * W_STRIDE];
    const float* wrow1 = &w_sh[(dl + 64) * W_STRIDE];
    const int num_tiles = (n_nodes + NT_OUT - 1) / NT_OUT;
    const int bstride = gridDim.x >> 1;

    for (int t = (blockIdx.x >> 1); t < num_tiles; t += bstride) {
        const int n0 = t * NT_OUT;
        const int nN = min(NT_OUT, n_nodes - n0);

        for (int i = tid; i < nN * 32; i += 128) {
            int n = i >> 5, q = i & 31;
            *(float4*)&x_sh[n * 128 + q * 4] =
                *(const float4*)&xsrc[(size_t)(n0 + n) * 128 + q * 4];
        }
        __syncthreads();

        float acc0[16], acc1[16];
#pragma unroll
        for (int n = 0; n < 16; n++) { acc0[n] = 0.f; acc1[n] = 0.f; }

        const float* xbase = &x_sh[nh * 16 * 128];
#pragma unroll
        for (int jq = 0; jq < 32; jq++) {
            float4 w0 = *(const float4*)&wrow0[jq * 4];
            float4 w1 = *(const float4*)&wrow1[jq * 4];
#pragma unroll
            for (int n = 0; n < 16; n++) {
                float4 x = *(const float4*)&xbase[n * 128 + jq * 4];
                acc0[n] = fmaf(x.w, w0.w, fmaf(x.z, w0.z,
                          fmaf(x.y, w0.y, fmaf(x.x, w0.x, acc0[n]))));
                acc1[n] = fmaf(x.w, w1.w, fmaf(x.z, w1.z,
                          fmaf(x.y, w1.y, fmaf(x.x, w1.x, acc1[n]))));
            }
        }

#pragma unroll
        for (int n = 0; n < 16; n++) {
            res_sh[(nh * 16 + n) * 128 + dl]      = acc0[n] + bc0;
            res_sh[(nh * 16 + n) * 128 + dl + 64] = acc1[n] + bc1;
        }
        __syncthreads();

        const int warp = tid >> 5, lane = tid & 31;
        for (int n = warp; n < nN; n += 4) {
            float4 v = *(const float4*)&res_sh[n * 128 + lane * 4];
            atomicAdd((float4*)&out[(size_t)(n0 + n) * 128 + lane * 4], v);
        }
        __syncthreads();
    }
}

// ---------------------------------------------------------------------------
// Launch
// ---------------------------------------------------------------------------
extern "C" void kernel_launch(void* const* d_in, const int* in_sizes, int n_in,
                              void* d_out, int out_size)
{
    const int*   node_type = (const int*)  d_in[0];
    const float* x_nodes   = (const float*)d_in[1];
    const int*   src       = (const int*)  d_in[2];
    const int*   dst       = (const int*)  d_in[3];
    const float* rbf       = (const float*)d_in[4];
    const float* dist      = (const float*)d_in[5];
    const float* emb       = (const float*)d_in[6];
    const float* W_e       = (const float*)d_in[7];
    const float* b_e       = (const float*)d_in[8];
    const float* W_c       = (const float*)d_in[9];
    const float* b_c       = (const float*)d_in[10];
    float* out = (float*)d_out;

    const int n_nodes = in_sizes[0];
    const int n_edges = in_sizes[2];

    // 1) zero accumulator and output together
    float* g_acc_ptr = nullptr;
    cudaGetSymbolAddress((void**)&g_acc_ptr, g_acc);
    int n4 = n_nodes * D_DIM / 4;
    zero2_kernel<<<(n4 + 255) / 256, 256>>>((float4*)g_acc_ptr, (float4*)out, n4);

    // 2) edge projection (TF32 MMA) + gather-multiply-scatter
    edge_kernel<<<592, 128>>>(rbf, dist, src, dst, node_type, emb, W_e, b_e, n_edges);

    // 3) final combine GEMM (half-j per block, DT=2)
    size_t shmem = (128 * W_STRIDE + 2 * NT_OUT * 128) * sizeof(float);
    cudaFuncSetAttribute(out_kernel, cudaFuncAttributeMaxDynamicSharedMemorySize, (int)shmem);
    out_kernel<<<296, 128, shmem>>>(x_nodes, W_c, b_c, out, n_nodes);
}